// round 12
// baseline (speedup 1.0000x reference)
#include <cuda_runtime.h>

#define BB 16
#define CC 1024
#define DD 128

__device__ float g_partial[1024];   // per-block exp-sum partials
__device__ int   g_count[BB];       // arrivals per batch (zero-init, self-reset)
__device__ int   g_depart[BB];      // departures per batch (zero-init, self-reset)

// ---------------------------------------------------------------------------
// Fused kernel, grid 1024 x 256, launch_bounds(256,6) -> 888 resident.
// Spin progress: blocks of a batch are contiguous; the resident window always
// contains whole completable batches which retire and admit stragglers.
//
//  Load balance (R10-proven): warp W owns candidates {W, 1023-W} in all 16
//    (b,p) rows of its batch -> ~16 valid slots/warp for any clen mix.
//    Ballot + compact into shared, PADDED with slot[0] dups so prefetch is
//    branch-free (dup loads are L2 hits; stores guarded by idx<nvalid).
//  Inner loop (NEW): software-pipelined. Iteration g computes FMAs from e*,
//    immediately issues iteration g+1's 4 LDG.128 into f*, then runs the
//    6-shuffle reduce + exp + store of g under those loads' latency.
//  Sync/Phase 2/reset: R7/R10-proven (atomic spin, fixed-order sums,
//    per-chunk scale+mask, departure reset). All sums bit-identical to R10.
//
//  Row-constant score terms cancel in softmax; |score| <~ 1 so exp without
//  max-subtraction matches reference exactly (validated R2-R11, ~1.2e-7).
// ---------------------------------------------------------------------------
__global__ void __launch_bounds__(256, 6) k_fused(
    const float* __restrict__ cand_emb,
    const int*   __restrict__ cand_len,
    const float* __restrict__ score_w,
    float* __restrict__ out)
{
    __shared__ int   s_slots[8][40];
    __shared__ float sred[8];
    __shared__ float s_inv;

    int blk = blockIdx.x;
    int b = blk >> 6;
    int t = threadIdx.x, wid = t >> 5, lane = t & 31;
    int hi16 = lane & 16, hi8 = lane & 8;

    float4 w4 = ((const float4*)(score_w + 3*DD))[lane];

    // ---- slot setup: warp W owns (bpl, W) and (bpl, 1023-W), bpl=0..15 ----
    int W = ((blk & 63) << 3) | wid;             // 0..511 within batch
    int bpl = lane >> 1;
    int myc = (lane & 1) ? (1023 - W) : W;
    int cl  = cand_len[(b << 4) + bpl];
    bool valid = myc < cl;
    unsigned vm = __ballot_sync(0xffffffffu, valid);
    int nvalid = __popc(vm);
    if (valid) {
        int pos = __popc(vm & ((1u << lane) - 1u));
        s_slots[wid][pos] = (bpl << 10) | myc;   // = bpl*1024 + c
    }
    __syncwarp();
    // pad 8 entries with slot[0] (safe dup) for branch-free prefetch
    if (nvalid > 0 && lane < 8) s_slots[wid][nvalid + lane] = s_slots[wid][0];
    __syncwarp();

    const float4* __restrict__ ceb =
        (const float4*)cand_emb + (((size_t)b << 4) * CC * DD) / 4;
    float* __restrict__ outb = out + ((size_t)b << 14);

    float wsum = 0.f;   // per-lane; fixed-order -> deterministic (== R10)
    int niter = (nvalid + 3) >> 2;
    if (niter > 0) {
        float4 e0 = ceb[(size_t)s_slots[wid][0]*32 + lane];
        float4 e1 = ceb[(size_t)s_slots[wid][1]*32 + lane];
        float4 e2 = ceb[(size_t)s_slots[wid][2]*32 + lane];
        float4 e3 = ceb[(size_t)s_slots[wid][3]*32 + lane];
        for (int g = 0; g < niter; g++) {
            // consume current loads into scalars (frees e* registers)
            float s0 = e0.x*w4.x + e0.y*w4.y + e0.z*w4.z + e0.w*w4.w;
            float s1 = e1.x*w4.x + e1.y*w4.y + e1.z*w4.z + e1.w*w4.w;
            float s2 = e2.x*w4.x + e2.y*w4.y + e2.z*w4.z + e2.w*w4.w;
            float s3 = e3.x*w4.x + e3.y*w4.y + e3.z*w4.z + e3.w*w4.w;
            // prefetch next group NOW (padded -> unconditional)
            int nb = (g + 1) << 2;
            float4 f0 = ceb[(size_t)s_slots[wid][nb+0]*32 + lane];
            float4 f1 = ceb[(size_t)s_slots[wid][nb+1]*32 + lane];
            float4 f2 = ceb[(size_t)s_slots[wid][nb+2]*32 + lane];
            float4 f3 = ceb[(size_t)s_slots[wid][nb+3]*32 + lane];
            // 6-shuffle multi-value reduction (runs under the f* loads)
            float ka = hi16 ? s1 : s0, sa = hi16 ? s0 : s1;
            float kc = hi16 ? s3 : s2, sc = hi16 ? s2 : s3;
            ka += __shfl_xor_sync(0xffffffffu, sa, 16);
            kc += __shfl_xor_sync(0xffffffffu, sc, 16);
            float ke = hi8 ? kc : ka, se = hi8 ? ka : kc;
            ke += __shfl_xor_sync(0xffffffffu, se, 8);
            ke += __shfl_xor_sync(0xffffffffu, ke, 4);
            ke += __shfl_xor_sync(0xffffffffu, ke, 2);
            ke += __shfl_xor_sync(0xffffffffu, ke, 1);
            // lanes 0/16/8/24 own sums of s0/s1/s2/s3 respectively
            if ((lane & 7) == 0) {
                int k = (hi16 ? 1 : 0) | (hi8 ? 2 : 0);
                int idx = (g << 2) + k;
                if (idx < nvalid) {
                    int pk = s_slots[wid][idx];
                    float x = __expf(ke);
                    outb[pk] = x;
                    wsum += x;
                }
            }
            e0 = f0; e1 = f1; e2 = f2; e3 = f3;
        }
    }

    // ---- fixed-order block partial, publish, per-batch spin (R7) ----
    #pragma unroll
    for (int o = 16; o > 0; o >>= 1)
        wsum += __shfl_xor_sync(0xffffffffu, wsum, o);
    if (lane == 0) sred[wid] = wsum;
    __syncthreads();
    if (t == 0) {
        float s = 0.f;
        #pragma unroll
        for (int w = 0; w < 8; w++) s += sred[w];
        g_partial[blk] = s;
        __threadfence();                          // release exps + partial
        atomicAdd(&g_count[b], 1);
        while (atomicAdd(&g_count[b], 0) < 64) __nanosleep(32);
        __threadfence();                          // acquire peers' data
    }
    __syncthreads();

    // ---- every block: identical fixed-order batch sum -> deterministic ----
    if (wid == 0) {
        float v = g_partial[b*64 + lane] + g_partial[b*64 + 32 + lane];
        #pragma unroll
        for (int o = 16; o > 0; o >>= 1)
            v += __shfl_xor_sync(0xffffffffu, v, o);
        if (lane == 0) s_inv = 1.0f / v;
    }
    __syncthreads();
    float inv = s_inv;

    // ---- scale own 256-slot chunk (single bp): valid -> *inv, masked -> 0 ----
    {
        int chunk_in_b = blk & 63;                // 64 chunks of 256 per batch
        int bplc = chunk_in_b >> 2;
        int cbase = (chunk_in_b & 3) << 8;
        int clenc = cand_len[(b << 4) + bplc];
        float* __restrict__ ochunk = outb + (chunk_in_b << 8);
        float val = ochunk[t];
        ochunk[t] = ((cbase + t) < clenc) ? val * inv : 0.0f;
    }

    // ---- reset counters for graph replay (after all batch spins exited) ----
    __syncthreads();
    if (t == 0) {
        int old = atomicAdd(&g_depart[b], 1);
        if (old == 63) { g_depart[b] = 0; g_count[b] = 0; }
    }
}

// ---------------------------------------------------------------------------
extern "C" void kernel_launch(void* const* d_in, const int* in_sizes, int n_in,
                              void* d_out, int out_size)
{
    const float* cand_emb = (const float*)d_in[3];
    const int*   cand_len = (const int*)  d_in[4];
    const float* score_w  = (const float*)d_in[19];
    float* out = (float*)d_out;

    k_fused<<<1024, 256>>>(cand_emb, cand_len, score_w, out);
}

// round 13
// speedup vs baseline: 1.1045x; 1.1045x over previous
#include <cuda_runtime.h>

#define BB 16
#define CC 1024
#define DD 128

__device__ float g_partial[1024];   // per-block exp-sum partials
__device__ int   g_count[BB];       // arrivals per batch (zero-init, self-reset)
__device__ int   g_depart[BB];      // departures per batch (zero-init, self-reset)

// ---------------------------------------------------------------------------
// Fused kernel, grid 1024 x 256, FULLY RESIDENT (launch_bounds(256,8);
// 32 regs x 2048 thr = full RF -> this budget is occupancy-critical).
// Structure == R10 winner; only change: streaming memory hints.
//
//  Load balance (R10-proven): warp W owns candidates {W, 1023-W} in all 16
//    (b,p) rows of its batch -> ~16 valid slots/warp for any clen mix.
//    Ballot + compact into shared; loop over valid candidates only.
//  Inner loop: 4 independent LDG.128 (now __ldcs: cand_emb is read-once ->
//    evict-first, no L1/L2 pollution), 6-shuffle multi-value reduction,
//    lanes 0/16/8/24 exp + __stcs store.
//  Sync: per-batch atomic spin (R7-proven). Phase 2: every block computes
//    the batch inv-sum in identical fixed order, scales its own 256-slot
//    chunk, zeroing masked slots. Reset via departure counter.
//
//  Row-constant score terms cancel in softmax; |score| <~ 1 so exp without
//  max-subtraction matches reference exactly (validated R2-R11, ~1.2e-7).
// ---------------------------------------------------------------------------
__global__ void __launch_bounds__(256, 8) k_fused(
    const float* __restrict__ cand_emb,
    const int*   __restrict__ cand_len,
    const float* __restrict__ score_w,
    float* __restrict__ out)
{
    __shared__ int   s_slots[8][33];
    __shared__ float sred[8];
    __shared__ float s_inv;

    int blk = blockIdx.x;
    int b = blk >> 6;
    int t = threadIdx.x, wid = t >> 5, lane = t & 31;
    int hi16 = lane & 16, hi8 = lane & 8;

    float4 w4 = ((const float4*)(score_w + 3*DD))[lane];

    // ---- slot setup: warp W owns (bpl, W) and (bpl, 1023-W), bpl=0..15 ----
    int W = ((blk & 63) << 3) | wid;             // 0..511 within batch
    int bpl = lane >> 1;
    int myc = (lane & 1) ? (1023 - W) : W;
    int cl  = cand_len[(b << 4) + bpl];
    bool valid = myc < cl;
    unsigned vm = __ballot_sync(0xffffffffu, valid);
    int nvalid = __popc(vm);
    if (valid) {
        int pos = __popc(vm & ((1u << lane) - 1u));
        s_slots[wid][pos] = (bpl << 10) | myc;   // = bpl*1024 + c
    }
    __syncwarp();

    const float4* __restrict__ ceb =
        (const float4*)cand_emb + (((size_t)b << 4) * CC * DD) / 4;
    float* __restrict__ outb = out + ((size_t)b << 14);

    float wsum = 0.f;   // per-lane; fixed-order accumulation -> deterministic
    for (int g = 0; g < nvalid; g += 4) {
        bool ok1 = g+1 < nvalid, ok2 = g+2 < nvalid, ok3 = g+3 < nvalid;
        int p0 = s_slots[wid][g];
        int p1 = s_slots[wid][ok1 ? g+1 : g];    // dup -> cache hit, branch-free
        int p2 = s_slots[wid][ok2 ? g+2 : g];
        int p3 = s_slots[wid][ok3 ? g+3 : g];
        float4 e0 = __ldcs(&ceb[(size_t)p0*32 + lane]);   // streaming: read-once
        float4 e1 = __ldcs(&ceb[(size_t)p1*32 + lane]);
        float4 e2 = __ldcs(&ceb[(size_t)p2*32 + lane]);
        float4 e3 = __ldcs(&ceb[(size_t)p3*32 + lane]);
        float s0 = e0.x*w4.x + e0.y*w4.y + e0.z*w4.z + e0.w*w4.w;
        float s1 = e1.x*w4.x + e1.y*w4.y + e1.z*w4.z + e1.w*w4.w;
        float s2 = e2.x*w4.x + e2.y*w4.y + e2.z*w4.z + e2.w*w4.w;
        float s3 = e3.x*w4.x + e3.y*w4.y + e3.z*w4.z + e3.w*w4.w;

        // --- 6-shuffle multi-value reduction (R9-proven) ---
        float ka = hi16 ? s1 : s0, sa = hi16 ? s0 : s1;
        float kc = hi16 ? s3 : s2, sc = hi16 ? s2 : s3;
        ka += __shfl_xor_sync(0xffffffffu, sa, 16);
        kc += __shfl_xor_sync(0xffffffffu, sc, 16);
        float ke = hi8 ? kc : ka, se = hi8 ? ka : kc;
        ke += __shfl_xor_sync(0xffffffffu, se, 8);
        ke += __shfl_xor_sync(0xffffffffu, ke, 4);
        ke += __shfl_xor_sync(0xffffffffu, ke, 2);
        ke += __shfl_xor_sync(0xffffffffu, ke, 1);
        // lanes 0..7 = sum(s0), 8..15 = sum(s2), 16..23 = sum(s1), 24..31 = sum(s3)
        if ((lane & 7) == 0) {
            int k = (hi16 ? 1 : 0) | (hi8 ? 2 : 0);
            bool okk = (k == 0) | (k == 1 ? ok1 : (k == 2 ? ok2 : ok3));
            if (okk) {
                int pk = (k == 0) ? p0 : (k == 1) ? p1 : (k == 2) ? p2 : p3;
                float x = __expf(ke);
                __stcs(&outb[pk], x);            // streaming store (reread once)
                wsum += x;
            }
        }
    }

    // ---- fixed-order block partial, publish, per-batch spin (R7) ----
    #pragma unroll
    for (int o = 16; o > 0; o >>= 1)
        wsum += __shfl_xor_sync(0xffffffffu, wsum, o);
    if (lane == 0) sred[wid] = wsum;
    __syncthreads();
    if (t == 0) {
        float s = 0.f;
        #pragma unroll
        for (int w = 0; w < 8; w++) s += sred[w];
        g_partial[blk] = s;
        __threadfence();                          // release exps + partial
        atomicAdd(&g_count[b], 1);
        while (atomicAdd(&g_count[b], 0) < 64) __nanosleep(32);
        __threadfence();                          // acquire peers' data
    }
    __syncthreads();

    // ---- every block: identical fixed-order batch sum -> deterministic ----
    if (wid == 0) {
        float v = g_partial[b*64 + lane] + g_partial[b*64 + 32 + lane];
        #pragma unroll
        for (int o = 16; o > 0; o >>= 1)
            v += __shfl_xor_sync(0xffffffffu, v, o);
        if (lane == 0) s_inv = 1.0f / v;
    }
    __syncthreads();
    float inv = s_inv;

    // ---- scale own 256-slot chunk (single bp): valid -> *inv, masked -> 0 ----
    {
        int chunk_in_b = blk & 63;                // 64 chunks of 256 per batch
        int bplc = chunk_in_b >> 2;
        int cbase = (chunk_in_b & 3) << 8;
        int clenc = cand_len[(b << 4) + bplc];
        float* __restrict__ ochunk = outb + (chunk_in_b << 8);
        float val = ochunk[t];
        ochunk[t] = ((cbase + t) < clenc) ? val * inv : 0.0f;
    }

    // ---- reset counters for graph replay (after all batch spins exited) ----
    __syncthreads();
    if (t == 0) {
        int old = atomicAdd(&g_depart[b], 1);
        if (old == 63) { g_depart[b] = 0; g_count[b] = 0; }
    }
}

// ---------------------------------------------------------------------------
extern "C" void kernel_launch(void* const* d_in, const int* in_sizes, int n_in,
                              void* d_out, int out_size)
{
    const float* cand_emb = (const float*)d_in[3];
    const int*   cand_len = (const int*)  d_in[4];
    const float* score_w  = (const float*)d_in[19];
    float* out = (float*)d_out;

    k_fused<<<1024, 256>>>(cand_emb, cand_len, score_w, out);
}

// round 14
// speedup vs baseline: 1.2786x; 1.1577x over previous
#include <cuda_runtime.h>

#define BB 16
#define CC 1024
#define DD 128

__device__ float g_partial[1024];   // per-block exp-sum partials (overwritten each run)

// ---------------------------------------------------------------------------
// K1: phase 1 only — R10-proven structure, all synchronization removed.
// Grid 1024 x 256, fully resident (launch_bounds(256,8), 32 regs).
//  Warp W owns candidates {W, 1023-W} in all 16 (b,p) rows of its batch
//  (ballot + compact -> ~16 valid slots/warp for any clen mix). Inner loop:
//  4 independent LDG.128, 6-shuffle multi-value reduce, lanes 0/16/8/24
//  exp + store. Per-block fixed-order partial -> g_partial[blk].
//  Masked slots untouched (K2 zeroes them).
//  Row-constant score terms cancel in softmax; |score| <~ 1 so exp without
//  max-subtraction matches reference exactly (validated R2-R13, ~1.2e-7).
// ---------------------------------------------------------------------------
__global__ void __launch_bounds__(256, 8) k_scores(
    const float* __restrict__ cand_emb,
    const int*   __restrict__ cand_len,
    const float* __restrict__ score_w,
    float* __restrict__ out)
{
    __shared__ int   s_slots[8][33];
    __shared__ float sred[8];

    int blk = blockIdx.x;
    int b = blk >> 6;
    int t = threadIdx.x, wid = t >> 5, lane = t & 31;
    int hi16 = lane & 16, hi8 = lane & 8;

    float4 w4 = ((const float4*)(score_w + 3*DD))[lane];

    // ---- slot setup: warp W owns (bpl, W) and (bpl, 1023-W), bpl=0..15 ----
    int W = ((blk & 63) << 3) | wid;             // 0..511 within batch
    int bpl = lane >> 1;
    int myc = (lane & 1) ? (1023 - W) : W;
    int cl  = cand_len[(b << 4) + bpl];
    bool valid = myc < cl;
    unsigned vm = __ballot_sync(0xffffffffu, valid);
    int nvalid = __popc(vm);
    if (valid) {
        int pos = __popc(vm & ((1u << lane) - 1u));
        s_slots[wid][pos] = (bpl << 10) | myc;   // = bpl*1024 + c
    }
    __syncwarp();

    const float4* __restrict__ ceb =
        (const float4*)cand_emb + (((size_t)b << 4) * CC * DD) / 4;
    float* __restrict__ outb = out + ((size_t)b << 14);

    float wsum = 0.f;   // per-lane; fixed-order accumulation -> deterministic
    for (int g = 0; g < nvalid; g += 4) {
        bool ok1 = g+1 < nvalid, ok2 = g+2 < nvalid, ok3 = g+3 < nvalid;
        int p0 = s_slots[wid][g];
        int p1 = s_slots[wid][ok1 ? g+1 : g];    // dup -> cache hit, branch-free
        int p2 = s_slots[wid][ok2 ? g+2 : g];
        int p3 = s_slots[wid][ok3 ? g+3 : g];
        float4 e0 = ceb[(size_t)p0*32 + lane];
        float4 e1 = ceb[(size_t)p1*32 + lane];
        float4 e2 = ceb[(size_t)p2*32 + lane];
        float4 e3 = ceb[(size_t)p3*32 + lane];
        float s0 = e0.x*w4.x + e0.y*w4.y + e0.z*w4.z + e0.w*w4.w;
        float s1 = e1.x*w4.x + e1.y*w4.y + e1.z*w4.z + e1.w*w4.w;
        float s2 = e2.x*w4.x + e2.y*w4.y + e2.z*w4.z + e2.w*w4.w;
        float s3 = e3.x*w4.x + e3.y*w4.y + e3.z*w4.z + e3.w*w4.w;

        // --- 6-shuffle multi-value reduction (R9-proven) ---
        float ka = hi16 ? s1 : s0, sa = hi16 ? s0 : s1;
        float kc = hi16 ? s3 : s2, sc = hi16 ? s2 : s3;
        ka += __shfl_xor_sync(0xffffffffu, sa, 16);
        kc += __shfl_xor_sync(0xffffffffu, sc, 16);
        float ke = hi8 ? kc : ka, se = hi8 ? ka : kc;
        ke += __shfl_xor_sync(0xffffffffu, se, 8);
        ke += __shfl_xor_sync(0xffffffffu, ke, 4);
        ke += __shfl_xor_sync(0xffffffffu, ke, 2);
        ke += __shfl_xor_sync(0xffffffffu, ke, 1);
        // lanes 0..7 = sum(s0), 8..15 = sum(s2), 16..23 = sum(s1), 24..31 = sum(s3)
        if ((lane & 7) == 0) {
            int k = (hi16 ? 1 : 0) | (hi8 ? 2 : 0);
            bool okk = (k == 0) | (k == 1 ? ok1 : (k == 2 ? ok2 : ok3));
            if (okk) {
                int pk = (k == 0) ? p0 : (k == 1) ? p1 : (k == 2) ? p2 : p3;
                float x = __expf(ke);
                outb[pk] = x;
                wsum += x;
            }
        }
    }

    // ---- fixed-order block partial -> g_partial (no sync, no atomics) ----
    #pragma unroll
    for (int o = 16; o > 0; o >>= 1)
        wsum += __shfl_xor_sync(0xffffffffu, wsum, o);
    if (lane == 0) sred[wid] = wsum;
    __syncthreads();
    if (t == 0) {
        float s = 0.f;
        #pragma unroll
        for (int w = 0; w < 8; w++) s += sred[w];
        g_partial[blk] = s;
    }
}

// ---------------------------------------------------------------------------
// K2 (PDL secondary): prelaunched while K1 drains; gridsync waits for K1
// completion, then normalizes. Each block: fixed-order batch inv-sum from
// the 64 partials (deterministic), scale own 256-slot chunk (single bp),
// zero masked slots. Data is L2-hot (written by K1 moments earlier).
// ---------------------------------------------------------------------------
__global__ void __launch_bounds__(256) k_norm(
    const int* __restrict__ cand_len,
    float* __restrict__ out)
{
    cudaGridDependencySynchronize();

    __shared__ float s_inv;
    int blk = blockIdx.x;
    int b = blk >> 6;
    int t = threadIdx.x, wid = t >> 5, lane = t & 31;

    if (wid == 0) {
        float v = g_partial[b*64 + lane] + g_partial[b*64 + 32 + lane];
        #pragma unroll
        for (int o = 16; o > 0; o >>= 1)
            v += __shfl_xor_sync(0xffffffffu, v, o);
        if (lane == 0) s_inv = 1.0f / v;
    }
    __syncthreads();
    float inv = s_inv;

    int chunk_in_b = blk & 63;                    // 64 chunks of 256 per batch
    int bplc = chunk_in_b >> 2;
    int cbase = (chunk_in_b & 3) << 8;
    int clenc = cand_len[(b << 4) + bplc];
    float* __restrict__ ochunk = out + ((size_t)b << 14) + (chunk_in_b << 8);
    if ((cbase + t) < clenc) ochunk[t] *= inv;
    else                     ochunk[t] = 0.0f;
}

// ---------------------------------------------------------------------------
extern "C" void kernel_launch(void* const* d_in, const int* in_sizes, int n_in,
                              void* d_out, int out_size)
{
    const float* cand_emb = (const float*)d_in[3];
    const int*   cand_len = (const int*)  d_in[4];
    const float* score_w  = (const float*)d_in[19];
    float* out = (float*)d_out;

    k_scores<<<1024, 256>>>(cand_emb, cand_len, score_w, out);

    // PDL: allow k_norm to launch while k_scores drains; gridsync inside
    // k_norm provides the data dependency.
    cudaLaunchConfig_t cfg = {};
    cfg.gridDim = dim3(1024, 1, 1);
    cfg.blockDim = dim3(256, 1, 1);
    cfg.dynamicSmemBytes = 0;
    cfg.stream = 0;
    cudaLaunchAttribute attrs[1];
    attrs[0].id = cudaLaunchAttributeProgrammaticStreamSerialization;
    attrs[0].val.programmaticStreamSerializationAllowed = 1;
    cfg.attrs = attrs;
    cfg.numAttrs = 1;
    cudaLaunchKernelEx(&cfg, k_norm, cand_len, out);
}